// round 8
// baseline (speedup 1.0000x reference)
#include <cuda_runtime.h>
#include <cuda_bf16.h>

// RBFKernel: out[b,n,m] = exp(-(x1[b,n]-x2[b,m])^2 / (2*scale^2))
// B=4, N1=N2=8192, D=1. Output 268M fp32 (~1.07 GB) -> store-BW bound.
// exp on the FMA pipe (no MUFU).
// R5: 8 rows per block -> x2 loaded once per 8 output rows (load traffic /8),
// freeing L1tex/L2 wavefront slots for the stores.

#define RBF_B       4
#define RBF_N1      8192
#define RBF_N2      8192
#define RBF_THREADS 256
#define RBF_ROWS    8    // output rows per block (8192 % 8 == 0 -> same batch)

// Fast 2^x-based exp of (d*d*k), k = -log2(e)/(2*s^2).
// Degree-5 Taylor of 2^f on [-0.5, 0.5]: max rel err ~2.4e-6.
__device__ __forceinline__ float rbf_exp(float d, float k) {
    float y = d * d * k;                      // y <= 0
    y = fmaxf(y, -125.0f);                    // keep exponent-bit trick in normal range
    float z = y + 12582912.0f;                // round-to-nearest-int magic (1.5*2^23)
    int   n = __float_as_int(z) - 0x4B400000; // integer part
    float f = y - (z - 12582912.0f);          // frac in [-0.5, 0.5]
    float p =              1.33335581e-3f;
    p = fmaf(p, f,         9.61812910e-3f);
    p = fmaf(p, f,         5.55041087e-2f);
    p = fmaf(p, f,         2.40226507e-1f);
    p = fmaf(p, f,         6.93147181e-1f);
    p = fmaf(p, f,         1.0f);             // p = 2^f in [0.707, 1.415)
    return __int_as_float(__float_as_int(p) + (n << 23)); // p * 2^n
}

__global__ void __launch_bounds__(RBF_THREADS)
rbf_kernel(const float* __restrict__ x1,
           const float* __restrict__ x2,
           const float* __restrict__ scale,
           float* __restrict__ out) {
    const int row0 = blockIdx.x * RBF_ROWS;   // first of 8 rows; all same batch
    const int b    = row0 >> 13;              // row / 8192
    const float s  = __ldg(&scale[0]);
    const float k  = -0.72134752044f / (s * s);  // -log2(e)/2 / s^2

    float a[RBF_ROWS];
    #pragma unroll
    for (int r = 0; r < RBF_ROWS; ++r)
        a[r] = __ldg(&x1[row0 + r]);

    const float4* __restrict__ xv = (const float4*)(x2 + (size_t)b * RBF_N2);
    float4* __restrict__ ov = (float4*)(out + (size_t)row0 * RBF_N2);
    const int rowstride4 = RBF_N2 / 4;        // float4s per row

    #pragma unroll
    for (int j = 0; j < (RBF_N2 / 4) / RBF_THREADS; ++j) {
        const int idx = j * RBF_THREADS + threadIdx.x;
        const float4 v = xv[idx];             // one load serves 8 rows
        #pragma unroll
        for (int r = 0; r < RBF_ROWS; ++r) {
            float4 o;
            o.x = rbf_exp(a[r] - v.x, k);
            o.y = rbf_exp(a[r] - v.y, k);
            o.z = rbf_exp(a[r] - v.z, k);
            o.w = rbf_exp(a[r] - v.w, k);
            ov[(size_t)r * rowstride4 + idx] = o;
        }
    }
}

extern "C" void kernel_launch(void* const* d_in, const int* in_sizes, int n_in,
                              void* d_out, int out_size) {
    const float* x1    = (const float*)d_in[0];
    const float* x2    = (const float*)d_in[1];
    const float* scale = (const float*)d_in[2];
    float* out = (float*)d_out;

    rbf_kernel<<<(RBF_B * RBF_N1) / RBF_ROWS, RBF_THREADS>>>(x1, x2, scale, out);
}

// round 11
// speedup vs baseline: 1.1056x; 1.1056x over previous
#include <cuda_runtime.h>
#include <cuda_bf16.h>
#include <cstdint>

// RBFKernel: out[b,n,m] = exp(-(x1[b,n]-x2[b,m])^2 / (2*scale^2))
// B=4, N1=N2=8192, D=1. Output 268M fp32 (~1.07 GB) -> store-BW bound.
// R9: compute each output row into a 32KB smem buffer, then emit ONE linear
// 32KB TMA bulk store per block (cp.async.bulk). Removes STG wavefronts from
// the L1tex path and gives the DRAM controllers maximal page locality.

#define RBF_B       4
#define RBF_N1      8192
#define RBF_N2      8192
#define RBF_THREADS 256
#define RBF_ROW_BYTES (RBF_N2 * 4)   // 32768

// Fast 2^x-based exp of (d*d*k), k = -log2(e)/(2*s^2).
// Degree-5 Taylor of 2^f on [-0.5, 0.5]: max rel err ~2.4e-6.
__device__ __forceinline__ float rbf_exp(float d, float k) {
    float y = d * d * k;                      // y <= 0
    y = fmaxf(y, -125.0f);                    // keep exponent-bit trick in normal range
    float z = y + 12582912.0f;                // round-to-nearest-int magic (1.5*2^23)
    int   n = __float_as_int(z) - 0x4B400000; // integer part
    float f = y - (z - 12582912.0f);          // frac in [-0.5, 0.5]
    float p =              1.33335581e-3f;
    p = fmaf(p, f,         9.61812910e-3f);
    p = fmaf(p, f,         5.55041087e-2f);
    p = fmaf(p, f,         2.40226507e-1f);
    p = fmaf(p, f,         6.93147181e-1f);
    p = fmaf(p, f,         1.0f);             // p = 2^f in [0.707, 1.415)
    return __int_as_float(__float_as_int(p) + (n << 23)); // p * 2^n
}

__device__ __forceinline__ uint32_t smem_u32(const void* p) {
    uint32_t a;
    asm("{ .reg .u64 t; cvta.to.shared.u64 t, %1; cvt.u32.u64 %0, t; }"
        : "=r"(a) : "l"(p));
    return a;
}

__global__ void __launch_bounds__(RBF_THREADS)
rbf_kernel(const float* __restrict__ x1,
           const float* __restrict__ x2,
           const float* __restrict__ scale,
           float* __restrict__ out) {
    __shared__ __align__(128) float buf[RBF_N2];   // 32 KB, one full output row

    const int row = blockIdx.x;          // 0 .. B*N1-1
    const int b   = row >> 13;           // row / 8192
    const float a = __ldg(&x1[row]);
    const float s = __ldg(&scale[0]);
    const float k = -0.72134752044f / (s * s);   // -log2(e)/2 / s^2

    const float4* __restrict__ xv = (const float4*)(x2 + (size_t)b * RBF_N2);
    float4* bv = (float4*)buf;

    #pragma unroll
    for (int j = 0; j < (RBF_N2 / 4) / RBF_THREADS; ++j) {
        const int idx = j * RBF_THREADS + threadIdx.x;
        const float4 v = xv[idx];
        float4 o;
        o.x = rbf_exp(a - v.x, k);
        o.y = rbf_exp(a - v.y, k);
        o.z = rbf_exp(a - v.z, k);
        o.w = rbf_exp(a - v.w, k);
        bv[idx] = o;                      // STS.128, conflict-free
    }
    __syncthreads();

    if (threadIdx.x == 0) {
        // Make generic-proxy smem writes visible to the async (TMA) proxy.
        asm volatile("fence.proxy.async.shared::cta;" ::: "memory");
        float* dst = out + (size_t)row * RBF_N2;
        uint32_t src = smem_u32(buf);
        asm volatile(
            "cp.async.bulk.global.shared::cta.bulk_group [%0], [%1], %2;"
            :: "l"(dst), "r"(src), "r"((uint32_t)RBF_ROW_BYTES)
            : "memory");
        asm volatile("cp.async.bulk.commit_group;" ::: "memory");
        // Wait until smem has been fully READ by the bulk engine; the global
        // writes themselves are guaranteed visible at kernel completion.
        asm volatile("cp.async.bulk.wait_group.read 0;" ::: "memory");
    }
}

extern "C" void kernel_launch(void* const* d_in, const int* in_sizes, int n_in,
                              void* d_out, int out_size) {
    const float* x1    = (const float*)d_in[0];
    const float* x2    = (const float*)d_in[1];
    const float* scale = (const float*)d_in[2];
    float* out = (float*)d_out;

    rbf_kernel<<<RBF_B * RBF_N1, RBF_THREADS>>>(x1, x2, scale, out);
}